// round 1
// baseline (speedup 1.0000x reference)
#include <cuda_runtime.h>

// Problem constants
#define NB     32
#define TT     4096
#define ENC_H  512
#define ATT_H  256
#define DEC_H  512
#define OUTD   80
#define SPK    64
#define KW     31
#define NWMAX  19   // 2*ATT_RANGE - 1

// Device scratch (no allocations allowed)
__device__ int   d_lo[NB];
__device__ int   d_nwin[NB];
__device__ float d_bias[NB][ATT_H];            // in_att_dec + softsign(spkr@W_spkr) + speed*W_speed
__device__ float d_logit_part[NB][NWMAX][8];   // per channel-group partial logits

// ---------------------------------------------------------------------------
// Kernel 1: per-batch prep. Zero output slice, argmax(prev_attention), prenet,
// per-channel bias. grid=32 blocks, 256 threads.
// ---------------------------------------------------------------------------
__global__ __launch_bounds__(256) void k_prep(
    const float* __restrict__ input_dec,    // [N,1,80]
    const float* __restrict__ prev_att,     // [N,T,1]
    const float* __restrict__ spkr,         // [N,1,64]
    const int*   __restrict__ lengths,      // [N]
    const float* __restrict__ speed,        // [N]
    const float* __restrict__ W_spkr,       // [64,256]
    const float* __restrict__ W_dec,        // [512,256]
    const float* __restrict__ W_speed,      // [1,256]
    const float* __restrict__ Wp1,          // [144,1024]
    const float* __restrict__ bp1,          // [1024]
    const float* __restrict__ Wp2,          // [1024,512]
    const float* __restrict__ bp2,          // [512]
    float* __restrict__ out)                // [N,T,1]
{
    const int b   = blockIdx.x;
    const int tid = threadIdx.x;

    __shared__ float dec_s[144];
    __shared__ float h_s[1024];
    __shared__ float p_s[512];
    __shared__ float rv[256];
    __shared__ int   ri[256];

    // ---- zero this batch's output slice (4096 floats, float4) ----
    {
        float4* o4 = (float4*)(out + (size_t)b * TT);
        float4 z = make_float4(0.f, 0.f, 0.f, 0.f);
        #pragma unroll
        for (int i = 0; i < 4; i++) o4[tid + i * 256] = z;
    }

    // ---- argmax over prev_attention[b,:,0] (first max wins) ----
    {
        const float* pa = prev_att + (size_t)b * TT;
        float bv = -1.0f; int bi = 0;
        #pragma unroll 4
        for (int t = tid; t < TT; t += 256) {
            float v = pa[t];
            if (v > bv) { bv = v; bi = t; }
        }
        rv[tid] = bv; ri[tid] = bi;
        __syncthreads();
        for (int s = 128; s > 0; s >>= 1) {
            if (tid < s) {
                float ov = rv[tid + s]; int oi = ri[tid + s];
                if (ov > rv[tid] || (ov == rv[tid] && oi < ri[tid])) {
                    rv[tid] = ov; ri[tid] = oi;
                }
            }
            __syncthreads();
        }
        if (tid == 0) {
            int mi = ri[0];
            int lo = max(mi - 9, 0);
            int hi = min(mi + 9, lengths[b] - 1);
            d_lo[b]   = lo;
            d_nwin[b] = hi - lo + 1;
        }
    }

    // ---- dec_in = concat(input_dec, spkr) -> smem ----
    if (tid < OUTD)            dec_s[tid] = input_dec[b * OUTD + tid];
    else if (tid < OUTD + SPK) dec_s[tid] = spkr[b * SPK + (tid - OUTD)];
    __syncthreads();

    // ---- h = relu(dec_in @ Wp1 + bp1), 1024 outputs, 4/thread ----
    {
        float a0 = bp1[tid], a1 = bp1[tid + 256], a2 = bp1[tid + 512], a3 = bp1[tid + 768];
        #pragma unroll 4
        for (int k = 0; k < 144; k++) {
            float d = dec_s[k];
            const float* w = Wp1 + k * 1024;
            a0 = fmaf(d, w[tid],       a0);
            a1 = fmaf(d, w[tid + 256], a1);
            a2 = fmaf(d, w[tid + 512], a2);
            a3 = fmaf(d, w[tid + 768], a3);
        }
        h_s[tid]       = fmaxf(a0, 0.f);
        h_s[tid + 256] = fmaxf(a1, 0.f);
        h_s[tid + 512] = fmaxf(a2, 0.f);
        h_s[tid + 768] = fmaxf(a3, 0.f);
    }
    __syncthreads();

    // ---- pout = relu(h @ Wp2 + bp2), 512 outputs, 2/thread ----
    {
        float p0 = bp2[tid], p1 = bp2[tid + 256];
        #pragma unroll 8
        for (int k = 0; k < 1024; k++) {
            float hk = h_s[k];
            const float* w = Wp2 + k * 512;
            p0 = fmaf(hk, w[tid],       p0);
            p1 = fmaf(hk, w[tid + 256], p1);
        }
        p_s[tid]       = fmaxf(p0, 0.f);
        p_s[tid + 256] = fmaxf(p1, 0.f);
    }
    __syncthreads();

    // ---- bias[c] = pout @ W_dec[:,c] + softsign(spkr @ W_spkr[:,c]) + speed*W_speed[c] ----
    {
        const int c = tid;
        float acc = 0.f;
        #pragma unroll 8
        for (int k = 0; k < 512; k++) acc = fmaf(p_s[k], W_dec[k * ATT_H + c], acc);
        float sa = 0.f;
        #pragma unroll
        for (int k = 0; k < SPK; k++) sa = fmaf(dec_s[OUTD + k], W_spkr[k * ATT_H + c], sa);
        acc += sa / (1.f + fabsf(sa));               // softsign
        acc = fmaf(speed[b], W_speed[c], acc);
        d_bias[b][c] = acc;
    }
}

// ---------------------------------------------------------------------------
// Kernel 2: windowed logit partials. grid = (8 channel-groups, 32 batches),
// 256 threads: tid -> (c_local = tid&31, kq = tid>>5), kq splits ENC_H into 8x64.
// ---------------------------------------------------------------------------
__global__ __launch_bounds__(256) void k_window(
    const float* __restrict__ input_enc,    // [N,T,512]
    const float* __restrict__ prev_att,     // [N,T,1]
    const float* __restrict__ W_enc,        // [512,256]
    const float* __restrict__ b_enc,        // [256]
    const float* __restrict__ conv_w,       // [256,1,31]
    const float* __restrict__ W_proj)       // [256,1]
{
    const int b  = blockIdx.y;
    const int cg = blockIdx.x;
    const int c0 = cg * 32;
    const int tid = threadIdx.x;
    const int cl = tid & 31;
    const int kq = tid >> 5;
    const int c  = c0 + cl;

    __shared__ float enc_s[NWMAX][ENC_H];   // 38 KB
    __shared__ float pa_s[NWMAX + 30 + 3];
    __shared__ float convw_s[32 * KW];
    __shared__ float bias_s[32], benc_s[32], wproj_s[32];
    __shared__ float red_s[32][9];          // padded stride 9

    const int lo   = d_lo[b];
    const int nwin = d_nwin[b];

    // load enc rows for the window (float4 coalesced)
    {
        const float4* enc4 = (const float4*)(input_enc + (size_t)b * TT * ENC_H);
        const int n4 = nwin * (ENC_H / 4);
        for (int i = tid; i < n4; i += 256) {
            int t = i >> 7, kk = i & 127;
            ((float4*)enc_s[t])[kk] = enc4[(size_t)(lo + t) * (ENC_H / 4) + kk];
        }
    }
    // prev_attention window with conv halo [lo-15, lo+nwin+14]
    for (int i = tid; i < nwin + 30; i += 256) {
        int p = lo - 15 + i;
        pa_s[i] = (p >= 0 && p < TT) ? prev_att[(size_t)b * TT + p] : 0.f;
    }
    // conv weight slice for this channel group
    for (int i = tid; i < 32 * KW; i += 256) convw_s[i] = conv_w[c0 * KW + i];
    if (tid < 32) {
        bias_s[tid]  = d_bias[b][c0 + tid];
        benc_s[tid]  = b_enc[c0 + tid];
        wproj_s[tid] = W_proj[c0 + tid];
    }
    __syncthreads();

    // main matvec: acc[t] = sum over this thread's 64 k of enc[t][k]*W_enc[k][c]
    float acc[NWMAX];
    #pragma unroll
    for (int t = 0; t < NWMAX; t++) acc[t] = 0.f;

    const int kbase = kq * 64;
    #pragma unroll 2
    for (int k = kbase; k < kbase + 64; k++) {
        float w = W_enc[k * ATT_H + c];     // coalesced across warp
        #pragma unroll
        for (int t = 0; t < NWMAX; t++)     // smem broadcast reads
            acc[t] = fmaf(enc_s[t][k], w, acc[t]);
    }

    // per-t: reduce kq partials, add biases + conv, tanh, project, reduce over channels
    for (int t = 0; t < nwin; t++) {
        red_s[cl][kq] = acc[t];
        __syncthreads();
        if (tid < 32) {
            float s = 0.f;
            #pragma unroll
            for (int q = 0; q < 8; q++) s += red_s[tid][q];
            s += benc_s[tid];
            s = s / (1.f + fabsf(s));       // softsign(enc @ W_enc + b_enc)
            s += bias_s[tid];
            float cv = 0.f;
            #pragma unroll
            for (int j = 0; j < KW; j++) cv = fmaf(pa_s[t + j], convw_s[tid * KW + j], cv);
            s += cv;
            float v = tanhf(s) * wproj_s[tid];
            #pragma unroll
            for (int o = 16; o > 0; o >>= 1) v += __shfl_down_sync(0xffffffffu, v, o);
            if (tid == 0) d_logit_part[b][t][cg] = v;
        }
        __syncthreads();
    }
}

// ---------------------------------------------------------------------------
// Kernel 3: per-batch softmax over the window. grid=32, 32 threads.
// ---------------------------------------------------------------------------
__global__ __launch_bounds__(32) void k_softmax(float* __restrict__ out)
{
    const int b = blockIdx.x;
    const int t = threadIdx.x;
    const int lo   = d_lo[b];
    const int nwin = d_nwin[b];

    float lg = -1e30f;
    if (t < nwin) {
        float s = 0.f;
        #pragma unroll
        for (int q = 0; q < 8; q++) s += d_logit_part[b][t][q];
        lg = s;
    }
    float m = lg;
    #pragma unroll
    for (int o = 16; o > 0; o >>= 1) m = fmaxf(m, __shfl_xor_sync(0xffffffffu, m, o));
    float e = (t < nwin) ? expf(lg - m) : 0.f;
    float sum = e;
    #pragma unroll
    for (int o = 16; o > 0; o >>= 1) sum += __shfl_xor_sync(0xffffffffu, sum, o);
    if (t < nwin) out[(size_t)b * TT + lo + t] = e / sum;
}

// ---------------------------------------------------------------------------
// launch
// ---------------------------------------------------------------------------
extern "C" void kernel_launch(void* const* d_in, const int* in_sizes, int n_in,
                              void* d_out, int out_size)
{
    const float* input_enc = (const float*)d_in[0];
    const float* input_dec = (const float*)d_in[1];
    const float* prev_att  = (const float*)d_in[2];
    const float* spkr      = (const float*)d_in[3];
    const int*   lengths   = (const int*)  d_in[4];
    const float* speed     = (const float*)d_in[5];
    const float* W_enc     = (const float*)d_in[6];
    const float* b_enc     = (const float*)d_in[7];
    const float* W_spkr    = (const float*)d_in[8];
    const float* conv_w    = (const float*)d_in[9];
    const float* W_dec     = (const float*)d_in[10];
    const float* W_speed   = (const float*)d_in[11];
    const float* Wp1       = (const float*)d_in[12];
    const float* bp1       = (const float*)d_in[13];
    const float* Wp2       = (const float*)d_in[14];
    const float* bp2       = (const float*)d_in[15];
    const float* W_proj    = (const float*)d_in[16];
    // d_in[17] = b_proj: constant shift, cancels in the masked softmax.

    float* out = (float*)d_out;

    k_prep<<<NB, 256>>>(input_dec, prev_att, spkr, lengths, speed,
                        W_spkr, W_dec, W_speed, Wp1, bp1, Wp2, bp2, out);
    k_window<<<dim3(8, NB), 256>>>(input_enc, prev_att, W_enc, b_enc, conv_w, W_proj);
    k_softmax<<<NB, 32>>>(out);
}

// round 2
// speedup vs baseline: 1.9152x; 1.9152x over previous
#include <cuda_runtime.h>

// Problem constants
#define NB     32
#define TT     4096
#define ENC_H  512
#define ATT_H  256
#define OUTD   80
#define SPK    64
#define KW     31
#define NWMAX  19   // 2*ATT_RANGE - 1

// Device scratch (no allocations allowed)
__device__ int   d_lo[NB];
__device__ int   d_nwin[NB];
__device__ float d_h[NB][1024];                // prenet layer-1 output
__device__ float d_p2part[8][NB][512];         // prenet layer-2 split-K partials
__device__ float d_biaspart[5][NB][ATT_H];     // 4x W_dec split-K + 1x (spkr+speed)
__device__ float d_logit_part[NB][NWMAX][8];   // per channel-group partial logits

// ---------------------------------------------------------------------------
// k_misc: per-batch. Zero output slice, argmax(prev_attention) -> window,
// spkr softsign bias + speed bias. grid=32, 512 threads.
// ---------------------------------------------------------------------------
__global__ __launch_bounds__(512) void k_misc(
    const float* __restrict__ prev_att,     // [N,T,1]
    const float* __restrict__ spkr,         // [N,1,64]
    const int*   __restrict__ lengths,      // [N]
    const float* __restrict__ speed,        // [N]
    const float* __restrict__ W_spkr,       // [64,256]
    const float* __restrict__ W_speed,      // [1,256]
    float* __restrict__ out)                // [N,T,1]
{
    const int b   = blockIdx.x;
    const int tid = threadIdx.x;

    __shared__ float rv[512];
    __shared__ int   ri[512];

    // zero this batch's output slice (4096 floats = 1024 float4)
    {
        float4* o4 = (float4*)(out + (size_t)b * TT);
        float4 z = make_float4(0.f, 0.f, 0.f, 0.f);
        o4[tid] = z;
        o4[tid + 512] = z;
    }

    // blocked argmax (first max wins): thread handles [tid*8, tid*8+8)
    {
        const float4* pa4 = (const float4*)(prev_att + (size_t)b * TT);
        float4 v0 = pa4[tid * 2];
        float4 v1 = pa4[tid * 2 + 1];
        float vals[8] = {v0.x, v0.y, v0.z, v0.w, v1.x, v1.y, v1.z, v1.w};
        float bv = -1.0f; int bi = 0;
        #pragma unroll
        for (int j = 0; j < 8; j++)
            if (vals[j] > bv) { bv = vals[j]; bi = tid * 8 + j; }
        rv[tid] = bv; ri[tid] = bi;
    }
    __syncthreads();
    for (int s = 256; s > 0; s >>= 1) {
        if (tid < s) {
            float ov = rv[tid + s]; int oi = ri[tid + s];
            if (ov > rv[tid] || (ov == rv[tid] && oi < ri[tid])) {
                rv[tid] = ov; ri[tid] = oi;
            }
        }
        __syncthreads();
    }
    if (tid == 0) {
        int mi = ri[0];
        int lo = max(mi - 9, 0);
        int hi = min(mi + 9, lengths[b] - 1);
        d_lo[b]   = lo;
        d_nwin[b] = hi - lo + 1;
    }

    // spkr softsign bias + speed bias, one channel per thread (tid < 256)
    if (tid < ATT_H) {
        const int c = tid;
        float sa = 0.f;
        #pragma unroll 8
        for (int j = 0; j < SPK; j++)
            sa = fmaf(spkr[b * SPK + j], W_spkr[j * ATT_H + c], sa);
        float v = sa / (1.f + fabsf(sa));
        v = fmaf(speed[b], W_speed[c], v);
        d_biaspart[4][b][c] = v;
    }
}

// ---------------------------------------------------------------------------
// k_prenet1: h = relu(concat(dec,spkr) @ Wp1 + bp1) for all batches.
// grid = 128 blocks (8 output channels each), 256 threads = 32 b x 8 c.
// ---------------------------------------------------------------------------
__global__ __launch_bounds__(256) void k_prenet1(
    const float* __restrict__ input_dec,    // [N,1,80]
    const float* __restrict__ spkr,         // [N,1,64]
    const float* __restrict__ Wp1,          // [144,1024]
    const float* __restrict__ bp1)          // [1024]
{
    const int cbase = blockIdx.x * 8;
    const int tid = threadIdx.x;
    const int b  = tid & 31;
    const int cc = tid >> 5;

    __shared__ float dec_s[32][145];   // pad 145 (stride mod 32 = 17, conflict-free)
    __shared__ float w_s[144][8];

    for (int i = tid; i < NB * OUTD; i += 256) {
        int b2 = i / OUTD, k = i - b2 * OUTD;
        dec_s[b2][k] = input_dec[i];
    }
    for (int i = tid; i < NB * SPK; i += 256) {
        int b2 = i >> 6, k = i & 63;
        dec_s[b2][OUTD + k] = spkr[i];
    }
    for (int i = tid; i < 144 * 8; i += 256) {
        int k = i >> 3, c2 = i & 7;
        w_s[k][c2] = Wp1[k * 1024 + cbase + c2];
    }
    __syncthreads();

    float acc = bp1[cbase + cc];
    #pragma unroll 8
    for (int k = 0; k < 144; k++)
        acc = fmaf(dec_s[b][k], w_s[k][cc], acc);
    d_h[b][cbase + cc] = fmaxf(acc, 0.f);
}

// ---------------------------------------------------------------------------
// k_prenet2: split-K partials of h @ Wp2. grid = (16 cgroups, 8 ksplits),
// 256 threads = 32 b x 8 s (4 channels per thread). K tile = 128.
// ---------------------------------------------------------------------------
__global__ __launch_bounds__(256) void k_prenet2(
    const float* __restrict__ Wp2)          // [1024,512]
{
    const int cb = blockIdx.x * 32;
    const int ks = blockIdx.y;
    const int k0 = ks * 128;
    const int tid = threadIdx.x;
    const int b = tid & 31;
    const int s = tid >> 5;

    __shared__ float h_s[32][133];     // 133 mod 32 = 5, conflict-free scalar reads
    __shared__ float wt[128][36];      // row 36 floats: float4-aligned broadcast

    for (int i = tid; i < 32 * 128; i += 256) {
        int b2 = i >> 7, kk = i & 127;
        h_s[b2][kk] = d_h[b2][k0 + kk];
    }
    for (int i = tid; i < 128 * 32; i += 256) {
        int kk = i >> 5, sc = i & 31;
        wt[kk][sc] = Wp2[(k0 + kk) * 512 + cb + sc];
    }
    __syncthreads();

    float4 acc = make_float4(0.f, 0.f, 0.f, 0.f);
    #pragma unroll 8
    for (int kk = 0; kk < 128; kk++) {
        float hv = h_s[b][kk];
        float4 w = *(const float4*)&wt[kk][s * 4];
        acc.x = fmaf(hv, w.x, acc.x);
        acc.y = fmaf(hv, w.y, acc.y);
        acc.z = fmaf(hv, w.z, acc.z);
        acc.w = fmaf(hv, w.w, acc.w);
    }
    *(float4*)&d_p2part[ks][b][cb + s * 4] = acc;
}

// ---------------------------------------------------------------------------
// k_bias: pout = relu(bp2 + sum of prenet2 partials); bias partial = pout@W_dec.
// grid = (8 cgroups, 4 ksplits), 256 threads = 32 b x 8 s (4 ch/thread).
// ---------------------------------------------------------------------------
__global__ __launch_bounds__(256) void k_bias(
    const float* __restrict__ W_dec,        // [512,256]
    const float* __restrict__ bp2)          // [512]
{
    const int cb = blockIdx.x * 32;
    const int ks = blockIdx.y;
    const int k0 = ks * 128;
    const int tid = threadIdx.x;
    const int b = tid & 31;
    const int s = tid >> 5;

    __shared__ float p_s[32][133];
    __shared__ float wdt[128][36];

    for (int i = tid; i < 32 * 128; i += 256) {
        int b2 = i >> 7, kk = i & 127;
        int k = k0 + kk;
        float v = bp2[k];
        #pragma unroll
        for (int j = 0; j < 8; j++) v += d_p2part[j][b2][k];
        p_s[b2][kk] = fmaxf(v, 0.f);
    }
    for (int i = tid; i < 128 * 32; i += 256) {
        int kk = i >> 5, sc = i & 31;
        wdt[kk][sc] = W_dec[(k0 + kk) * ATT_H + cb + sc];
    }
    __syncthreads();

    float4 acc = make_float4(0.f, 0.f, 0.f, 0.f);
    #pragma unroll 8
    for (int kk = 0; kk < 128; kk++) {
        float pv = p_s[b][kk];
        float4 w = *(const float4*)&wdt[kk][s * 4];
        acc.x = fmaf(pv, w.x, acc.x);
        acc.y = fmaf(pv, w.y, acc.y);
        acc.z = fmaf(pv, w.z, acc.z);
        acc.w = fmaf(pv, w.w, acc.w);
    }
    *(float4*)&d_biaspart[ks][b][cb + s * 4] = acc;
}

// ---------------------------------------------------------------------------
// k_window: windowed logits. grid = (8 cgroups, 32 batches), 256 threads.
// Thread = (cl = tid&15 -> channels c0+cl, c0+cl+16; kq = tid>>4 -> 32 k,
// visited as 8 k per 128-k tile). Matvec in registers, parallel tail.
// ---------------------------------------------------------------------------
__global__ __launch_bounds__(256) void k_window(
    const float* __restrict__ input_enc,    // [N,T,512]
    const float* __restrict__ prev_att,     // [N,T,1]
    const float* __restrict__ W_enc,        // [512,256]
    const float* __restrict__ b_enc,        // [256]
    const float* __restrict__ conv_w,       // [256,1,31]
    const float* __restrict__ W_proj)       // [256,1]
{
    const int b  = blockIdx.y;
    const int cg = blockIdx.x;
    const int c0 = cg * 32;
    const int tid = threadIdx.x;
    const int cl = tid & 15;
    const int kq = tid >> 4;
    const int ca = c0 + cl;
    const int cb2 = c0 + cl + 16;

    __shared__ float enc_t[NWMAX][132];       // one 128-k tile (float4 aligned rows)
    __shared__ float red_s[NWMAX][8][33];
    __shared__ float pa_s[NWMAX + 30 + 3];
    __shared__ float convw_s[32 * KW];
    __shared__ float bias_s[32], benc_s[32], wproj_s[32];

    const int lo   = d_lo[b];
    const int nwin = d_nwin[b];

    // small stages
    for (int i = tid; i < nwin + 30; i += 256) {
        int p = lo - 15 + i;
        pa_s[i] = (p >= 0 && p < TT) ? prev_att[(size_t)b * TT + p] : 0.f;
    }
    for (int i = tid; i < 32 * KW; i += 256) convw_s[i] = conv_w[c0 * KW + i];
    if (tid < 32) {
        float bsum = 0.f;
        #pragma unroll
        for (int j = 0; j < 5; j++) bsum += d_biaspart[j][b][c0 + tid];
        bias_s[tid]  = bsum;
        benc_s[tid]  = b_enc[c0 + tid];
        wproj_s[tid] = W_proj[c0 + tid];
    }

    float acc_a[NWMAX], acc_b[NWMAX];
    #pragma unroll
    for (int t = 0; t < NWMAX; t++) { acc_a[t] = 0.f; acc_b[t] = 0.f; }

    const float4* enc4 = (const float4*)(input_enc + (size_t)b * TT * ENC_H);

    for (int tile = 0; tile < 4; tile++) {
        __syncthreads();
        // stage enc tile: 19 rows x 128 floats = 608 float4 (clamped row: values
        // for t >= nwin are never consumed downstream)
        for (int i = tid; i < NWMAX * 32; i += 256) {
            int t = i >> 5, q = i & 31;
            int row = lo + t; if (row > TT - 1) row = TT - 1;
            float4 e = enc4[(size_t)row * (ENC_H / 4) + tile * 32 + q];
            *(float4*)&enc_t[t][q * 4] = e;
        }
        __syncthreads();

        #pragma unroll
        for (int k4 = 0; k4 < 2; k4++) {
            const int kk = kq * 8 + k4 * 4;
            const int kg = tile * 128 + kk;
            float4 wa, wb;
            wa.x = W_enc[(kg + 0) * ATT_H + ca];
            wa.y = W_enc[(kg + 1) * ATT_H + ca];
            wa.z = W_enc[(kg + 2) * ATT_H + ca];
            wa.w = W_enc[(kg + 3) * ATT_H + ca];
            wb.x = W_enc[(kg + 0) * ATT_H + cb2];
            wb.y = W_enc[(kg + 1) * ATT_H + cb2];
            wb.z = W_enc[(kg + 2) * ATT_H + cb2];
            wb.w = W_enc[(kg + 3) * ATT_H + cb2];
            #pragma unroll
            for (int t = 0; t < NWMAX; t++) {
                float4 e = *(const float4*)&enc_t[t][kk];
                acc_a[t] = fmaf(e.x, wa.x, acc_a[t]);
                acc_a[t] = fmaf(e.y, wa.y, acc_a[t]);
                acc_a[t] = fmaf(e.z, wa.z, acc_a[t]);
                acc_a[t] = fmaf(e.w, wa.w, acc_a[t]);
                acc_b[t] = fmaf(e.x, wb.x, acc_b[t]);
                acc_b[t] = fmaf(e.y, wb.y, acc_b[t]);
                acc_b[t] = fmaf(e.z, wb.z, acc_b[t]);
                acc_b[t] = fmaf(e.w, wb.w, acc_b[t]);
            }
        }
    }

    // combine the two kq halves within each warp, stash per-warp partials
    const int w = tid >> 5;
    #pragma unroll
    for (int t = 0; t < NWMAX; t++) {
        float va = acc_a[t] + __shfl_xor_sync(0xffffffffu, acc_a[t], 16);
        float vb = acc_b[t] + __shfl_xor_sync(0xffffffffu, acc_b[t], 16);
        if ((tid & 31) < 16) {
            red_s[t][w][cl]      = va;
            red_s[t][w][cl + 16] = vb;
        }
    }
    __syncthreads();

    // parallel tail: warp tq handles t = p*8 + tq
    const int c2 = tid & 31;
    const int tq = tid >> 5;
    #pragma unroll
    for (int p = 0; p < 3; p++) {
        const int t = p * 8 + tq;
        float v = 0.f;
        if (t < nwin) {
            float s = 0.f;
            #pragma unroll
            for (int q = 0; q < 8; q++) s += red_s[t][q][c2];
            s += benc_s[c2];
            s = s / (1.f + fabsf(s));       // softsign(enc @ W_enc + b_enc)
            s += bias_s[c2];
            float cv = 0.f;
            #pragma unroll
            for (int j = 0; j < KW; j++) cv = fmaf(pa_s[t + j], convw_s[c2 * KW + j], cv);
            s += cv;
            v = tanhf(s) * wproj_s[c2];
        }
        #pragma unroll
        for (int o = 16; o > 0; o >>= 1) v += __shfl_down_sync(0xffffffffu, v, o);
        if (c2 == 0 && t < nwin) d_logit_part[b][t][cg] = v;
    }
}

// ---------------------------------------------------------------------------
// k_softmax: per-batch softmax over the window. grid=32, 32 threads.
// ---------------------------------------------------------------------------
__global__ __launch_bounds__(32) void k_softmax(float* __restrict__ out)
{
    const int b = blockIdx.x;
    const int t = threadIdx.x;
    const int lo   = d_lo[b];
    const int nwin = d_nwin[b];

    float lg = -1e30f;
    if (t < nwin) {
        float s = 0.f;
        #pragma unroll
        for (int q = 0; q < 8; q++) s += d_logit_part[b][t][q];
        lg = s;
    }
    float m = lg;
    #pragma unroll
    for (int o = 16; o > 0; o >>= 1) m = fmaxf(m, __shfl_xor_sync(0xffffffffu, m, o));
    float e = (t < nwin) ? expf(lg - m) : 0.f;
    float sum = e;
    #pragma unroll
    for (int o = 16; o > 0; o >>= 1) sum += __shfl_xor_sync(0xffffffffu, sum, o);
    if (t < nwin) out[(size_t)b * TT + lo + t] = e / sum;
}

// ---------------------------------------------------------------------------
// launch
// ---------------------------------------------------------------------------
extern "C" void kernel_launch(void* const* d_in, const int* in_sizes, int n_in,
                              void* d_out, int out_size)
{
    const float* input_enc = (const float*)d_in[0];
    const float* input_dec = (const float*)d_in[1];
    const float* prev_att  = (const float*)d_in[2];
    const float* spkr      = (const float*)d_in[3];
    const int*   lengths   = (const int*)  d_in[4];
    const float* speed     = (const float*)d_in[5];
    const float* W_enc     = (const float*)d_in[6];
    const float* b_enc     = (const float*)d_in[7];
    const float* W_spkr    = (const float*)d_in[8];
    const float* conv_w    = (const float*)d_in[9];
    const float* W_dec     = (const float*)d_in[10];
    const float* W_speed   = (const float*)d_in[11];
    const float* Wp1       = (const float*)d_in[12];
    const float* bp1       = (const float*)d_in[13];
    const float* Wp2       = (const float*)d_in[14];
    const float* bp2       = (const float*)d_in[15];
    const float* W_proj    = (const float*)d_in[16];
    // d_in[17] = b_proj: constant shift, cancels in the masked softmax.

    float* out = (float*)d_out;

    k_misc   <<<NB, 512>>>(prev_att, spkr, lengths, speed, W_spkr, W_speed, out);
    k_prenet1<<<128, 256>>>(input_dec, spkr, Wp1, bp1);
    k_prenet2<<<dim3(16, 8), 256>>>(Wp2);
    k_bias   <<<dim3(8, 4), 256>>>(W_dec, bp2);
    k_window <<<dim3(8, NB), 256>>>(input_enc, prev_att, W_enc, b_enc, conv_w, W_proj);
    k_softmax<<<NB, 32>>>(out);
}

// round 3
// speedup vs baseline: 2.6498x; 1.3836x over previous
#include <cuda_runtime.h>

// Problem constants
#define NB     32
#define TT     4096
#define ENC_H  512
#define ATT_H  256
#define OUTD   80
#define SPK    64
#define KW     31
#define NWMAX  19   // 2*ATT_RANGE - 1

// Device scratch (no allocations allowed)
__device__ int          d_lo[NB];
__device__ int          d_nwin[NB];
__device__ unsigned int d_count[NB];
__device__ float        d_bias0[NB][ATT_H];          // softsign(spkr@W_spkr) + speed*W_speed
__device__ float        d_h[1024][NB];               // prenet layer-1 output, k-major
__device__ float        d_p2part[8][NB][512];        // prenet layer-2 split-K partials
__device__ float        d_logit_part[NB][NWMAX][8];  // per channel-group partial logits

// ---------------------------------------------------------------------------
// k_front: heterogeneous. Blocks 0..31: per-batch misc (zero out, argmax,
// spkr/speed bias, counter reset). Blocks 32..159: prenet1 (8 channels each).
// ---------------------------------------------------------------------------
__global__ __launch_bounds__(256) void k_front(
    const float* __restrict__ prev_att,     // [N,T,1]
    const float* __restrict__ input_dec,    // [N,1,80]
    const float* __restrict__ spkr,         // [N,1,64]
    const int*   __restrict__ lengths,      // [N]
    const float* __restrict__ speed,        // [N]
    const float* __restrict__ W_spkr,       // [64,256]
    const float* __restrict__ W_speed,      // [1,256]
    const float* __restrict__ Wp1,          // [144,1024]
    const float* __restrict__ bp1,          // [1024]
    float* __restrict__ out)                // [N,T,1]
{
    const int tid = threadIdx.x;

    if (blockIdx.x < NB) {
        const int b = blockIdx.x;
        __shared__ float rv[256];
        __shared__ int   ri[256];

        // zero this batch's output slice (4096 floats = 1024 float4)
        {
            float4* o4 = (float4*)(out + (size_t)b * TT);
            float4 z = make_float4(0.f, 0.f, 0.f, 0.f);
            o4[tid] = z; o4[tid + 256] = z; o4[tid + 512] = z; o4[tid + 768] = z;
        }
        if (tid == 0) d_count[b] = 0u;

        // blocked argmax, 16 elems/thread, first max wins
        {
            const float4* pa4 = (const float4*)(prev_att + (size_t)b * TT);
            float bv = -1.0f; int bi = 0;
            #pragma unroll
            for (int j = 0; j < 4; j++) {
                float4 v = pa4[tid * 4 + j];
                int base = tid * 16 + j * 4;
                if (v.x > bv) { bv = v.x; bi = base; }
                if (v.y > bv) { bv = v.y; bi = base + 1; }
                if (v.z > bv) { bv = v.z; bi = base + 2; }
                if (v.w > bv) { bv = v.w; bi = base + 3; }
            }
            rv[tid] = bv; ri[tid] = bi;
        }
        __syncthreads();
        for (int s = 128; s > 0; s >>= 1) {
            if (tid < s) {
                float ov = rv[tid + s]; int oi = ri[tid + s];
                if (ov > rv[tid] || (ov == rv[tid] && oi < ri[tid])) {
                    rv[tid] = ov; ri[tid] = oi;
                }
            }
            __syncthreads();
        }
        if (tid == 0) {
            int mi = ri[0];
            int lo = max(mi - 9, 0);
            int hi = min(mi + 9, lengths[b] - 1);
            d_lo[b]   = lo;
            d_nwin[b] = hi - lo + 1;
        }

        // spkr softsign bias + speed bias, one channel per thread
        {
            float sa = 0.f;
            #pragma unroll 8
            for (int j = 0; j < SPK; j++)
                sa = fmaf(spkr[b * SPK + j], W_spkr[j * ATT_H + tid], sa);
            float v = sa / (1.f + fabsf(sa));
            d_bias0[b][tid] = fmaf(speed[b], W_speed[tid], v);
        }
    } else {
        // prenet1: h = relu(concat(dec,spkr) @ Wp1 + bp1), 8 channels per block
        const int cbase = (blockIdx.x - NB) * 8;
        const int b  = tid & 31;
        const int cc = tid >> 5;

        __shared__ float dec_s[32][145];   // 145 mod 32 = 17, conflict-free
        __shared__ float w_s[144][8];

        for (int i = tid; i < NB * OUTD; i += 256) {
            int b2 = i / OUTD, k = i - b2 * OUTD;
            dec_s[b2][k] = input_dec[i];
        }
        for (int i = tid; i < NB * SPK; i += 256) {
            int b2 = i >> 6, k = i & 63;
            dec_s[b2][OUTD + k] = spkr[i];
        }
        for (int i = tid; i < 144 * 8; i += 256) {
            int k = i >> 3, c2 = i & 7;
            w_s[k][c2] = Wp1[k * 1024 + cbase + c2];
        }
        __syncthreads();

        float acc = bp1[cbase + cc];
        #pragma unroll 8
        for (int k = 0; k < 144; k++)
            acc = fmaf(dec_s[b][k], w_s[k][cc], acc);
        d_h[cbase + cc][b] = fmaxf(acc, 0.f);   // k-major store, coalesced over b
    }
}

// ---------------------------------------------------------------------------
// k_prenet2: split-K partials of h @ Wp2. grid = (16 cgroups, 8 ksplits),
// 256 threads = 32 b x 8 s (4 channels per thread). K tile = 128.
// ---------------------------------------------------------------------------
__global__ __launch_bounds__(256) void k_prenet2(
    const float* __restrict__ Wp2)          // [1024,512]
{
    const int cb = blockIdx.x * 32;
    const int ks = blockIdx.y;
    const int k0 = ks * 128;
    const int tid = threadIdx.x;
    const int b = tid & 31;
    const int s = tid >> 5;

    __shared__ float h_s[128][33];     // [k][b], 128B rows, conflict-free
    __shared__ float wt[128][36];      // [k][c], float4-aligned broadcast rows

    for (int i = tid; i < 32 * 128; i += 256) {
        int kk = i >> 5, b2 = i & 31;
        h_s[kk][b2] = d_h[k0 + kk][b2];                 // coalesced
    }
    for (int i = tid; i < 128 * 32; i += 256) {
        int kk = i >> 5, sc = i & 31;
        wt[kk][sc] = Wp2[(k0 + kk) * 512 + cb + sc];    // coalesced
    }
    __syncthreads();

    float4 acc = make_float4(0.f, 0.f, 0.f, 0.f);
    #pragma unroll 8
    for (int kk = 0; kk < 128; kk++) {
        float hv = h_s[kk][b];
        float4 w = *(const float4*)&wt[kk][s * 4];      // warp-uniform broadcast
        acc.x = fmaf(hv, w.x, acc.x);
        acc.y = fmaf(hv, w.y, acc.y);
        acc.z = fmaf(hv, w.z, acc.z);
        acc.w = fmaf(hv, w.w, acc.w);
    }
    *(float4*)&d_p2part[ks][b][cb + s * 4] = acc;
}

// ---------------------------------------------------------------------------
// k_window: fused bias + windowed logits + last-block softmax.
// grid = (8 cgroups, 32 batches), 256 threads.
// ---------------------------------------------------------------------------
__global__ __launch_bounds__(256) void k_window(
    const float* __restrict__ input_enc,    // [N,T,512]
    const float* __restrict__ prev_att,     // [N,T,1]
    const float* __restrict__ W_enc,        // [512,256]
    const float* __restrict__ b_enc,        // [256]
    const float* __restrict__ conv_w,       // [256,1,31]
    const float* __restrict__ W_proj,       // [256,1]
    const float* __restrict__ W_dec,        // [512,256]
    const float* __restrict__ bp2,          // [512]
    float* __restrict__ out)                // [N,T,1]
{
    const int b  = blockIdx.y;
    const int cg = blockIdx.x;
    const int c0 = cg * 32;
    const int tid = threadIdx.x;

    __shared__ float p_s[512];                // reconstructed prenet output
    __shared__ float enc_t[NWMAX][132];       // one 128-k tile (float4 aligned)
    __shared__ float red_s[NWMAX][8][33];
    __shared__ float pa_s[NWMAX + 30 + 3];
    __shared__ float convw_s[32 * KW];
    __shared__ float bias_s[32], benc_s[32], wproj_s[32];
    __shared__ int   last_s;

    const int lo   = d_lo[b];
    const int nwin = d_nwin[b];

    // ---- reconstruct pout = relu(bp2 + sum of split-K partials), 2 k/thread ----
    #pragma unroll
    for (int r = 0; r < 2; r++) {
        int k = tid + r * 256;
        float v = bp2[k];
        #pragma unroll
        for (int j = 0; j < 8; j++) v += d_p2part[j][b][k];
        p_s[k] = fmaxf(v, 0.f);
    }
    // prev_attention window with conv halo
    for (int i = tid; i < nwin + 30; i += 256) {
        int p = lo - 15 + i;
        pa_s[i] = (p >= 0 && p < TT) ? prev_att[(size_t)b * TT + p] : 0.f;
    }
    for (int i = tid; i < 32 * KW; i += 256) convw_s[i] = conv_w[c0 * KW + i];
    if (tid < 32) {
        benc_s[tid]  = b_enc[c0 + tid];
        wproj_s[tid] = W_proj[c0 + tid];
    }
    __syncthreads();

    // ---- bias slice: pout @ W_dec[:, c0..c0+32) + bias0 ----
    {
        const int cl = tid & 31, kq = tid >> 5;
        float acc = 0.f;
        #pragma unroll 8
        for (int j = 0; j < 64; j++) {
            int k = kq * 64 + j;
            acc = fmaf(p_s[k], W_dec[k * ATT_H + c0 + cl], acc);
        }
        red_s[0][kq][cl] = acc;
    }
    __syncthreads();
    if (tid < 32) {
        float s = d_bias0[b][c0 + tid];
        #pragma unroll
        for (int q = 0; q < 8; q++) s += red_s[0][q][tid];
        bias_s[tid] = s;
    }
    // (red_s[0] is re-used below, but only after the next __syncthreads())

    // ---- enc matvec: cl = tid&15 -> channels c0+cl, c0+cl+16; kq = tid>>4 ----
    const int cl  = tid & 15;
    const int kq  = tid >> 4;
    const int ca  = c0 + cl;
    const int cb2 = c0 + cl + 16;

    float acc_a[NWMAX], acc_b[NWMAX];
    #pragma unroll
    for (int t = 0; t < NWMAX; t++) { acc_a[t] = 0.f; acc_b[t] = 0.f; }

    const float4* enc4 = (const float4*)(input_enc + (size_t)b * TT * ENC_H);

    for (int tile = 0; tile < 4; tile++) {
        __syncthreads();
        for (int i = tid; i < NWMAX * 32; i += 256) {
            int t = i >> 5, q = i & 31;
            int row = lo + t; if (row > TT - 1) row = TT - 1;   // clamped, unused for t>=nwin
            float4 e = enc4[(size_t)row * (ENC_H / 4) + tile * 32 + q];
            *(float4*)&enc_t[t][q * 4] = e;
        }
        __syncthreads();

        #pragma unroll
        for (int k4 = 0; k4 < 2; k4++) {
            const int kk = kq * 8 + k4 * 4;
            const int kg = tile * 128 + kk;
            float4 wa, wb;
            wa.x = W_enc[(kg + 0) * ATT_H + ca];
            wa.y = W_enc[(kg + 1) * ATT_H + ca];
            wa.z = W_enc[(kg + 2) * ATT_H + ca];
            wa.w = W_enc[(kg + 3) * ATT_H + ca];
            wb.x = W_enc[(kg + 0) * ATT_H + cb2];
            wb.y = W_enc[(kg + 1) * ATT_H + cb2];
            wb.z = W_enc[(kg + 2) * ATT_H + cb2];
            wb.w = W_enc[(kg + 3) * ATT_H + cb2];
            #pragma unroll
            for (int t = 0; t < NWMAX; t++) {
                float4 e = *(const float4*)&enc_t[t][kk];
                acc_a[t] = fmaf(e.x, wa.x, acc_a[t]);
                acc_a[t] = fmaf(e.y, wa.y, acc_a[t]);
                acc_a[t] = fmaf(e.z, wa.z, acc_a[t]);
                acc_a[t] = fmaf(e.w, wa.w, acc_a[t]);
                acc_b[t] = fmaf(e.x, wb.x, acc_b[t]);
                acc_b[t] = fmaf(e.y, wb.y, acc_b[t]);
                acc_b[t] = fmaf(e.z, wb.z, acc_b[t]);
                acc_b[t] = fmaf(e.w, wb.w, acc_b[t]);
            }
        }
    }

    // combine the two kq halves within each warp, stash per-warp partials
    const int w = tid >> 5;
    #pragma unroll
    for (int t = 0; t < NWMAX; t++) {
        float va = acc_a[t] + __shfl_xor_sync(0xffffffffu, acc_a[t], 16);
        float vb = acc_b[t] + __shfl_xor_sync(0xffffffffu, acc_b[t], 16);
        if ((tid & 31) < 16) {
            red_s[t][w][cl]      = va;
            red_s[t][w][cl + 16] = vb;
        }
    }
    __syncthreads();

    // parallel tail: warp tq handles t = p*8 + tq
    const int c2 = tid & 31;
    const int tq = tid >> 5;
    #pragma unroll
    for (int p = 0; p < 3; p++) {
        const int t = p * 8 + tq;
        float v = 0.f;
        if (t < nwin) {
            float s = 0.f;
            #pragma unroll
            for (int q = 0; q < 8; q++) s += red_s[t][q][c2];
            s += benc_s[c2];
            s = s / (1.f + fabsf(s));       // softsign(enc @ W_enc + b_enc)
            s += bias_s[c2];
            float cv = 0.f;
            #pragma unroll
            for (int j = 0; j < KW; j++) cv = fmaf(pa_s[t + j], convw_s[c2 * KW + j], cv);
            s += cv;
            v = tanhf(s) * wproj_s[c2];
        }
        #pragma unroll
        for (int o = 16; o > 0; o >>= 1) v += __shfl_down_sync(0xffffffffu, v, o);
        if (c2 == 0 && t < nwin) d_logit_part[b][t][cg] = v;
    }

    // ---- last-block-done fused softmax ----
    __threadfence();
    __syncthreads();
    if (tid == 0) {
        unsigned int old = atomicAdd(&d_count[b], 1u);
        last_s = (old == 7u) ? 1 : 0;
    }
    __syncthreads();
    if (last_s && tid < 32) {
        const int t = tid;
        float lg = -1e30f;
        if (t < nwin) {
            float s = 0.f;
            #pragma unroll
            for (int q = 0; q < 8; q++) s += __ldcg(&d_logit_part[b][t][q]);
            lg = s;
        }
        float m = lg;
        #pragma unroll
        for (int o = 16; o > 0; o >>= 1) m = fmaxf(m, __shfl_xor_sync(0xffffffffu, m, o));
        float e = (t < nwin) ? expf(lg - m) : 0.f;
        float sum = e;
        #pragma unroll
        for (int o = 16; o > 0; o >>= 1) sum += __shfl_xor_sync(0xffffffffu, sum, o);
        if (t < nwin) out[(size_t)b * TT + lo + t] = e / sum;
    }
}

// ---------------------------------------------------------------------------
// launch
// ---------------------------------------------------------------------------
extern "C" void kernel_launch(void* const* d_in, const int* in_sizes, int n_in,
                              void* d_out, int out_size)
{
    const float* input_enc = (const float*)d_in[0];
    const float* input_dec = (const float*)d_in[1];
    const float* prev_att  = (const float*)d_in[2];
    const float* spkr      = (const float*)d_in[3];
    const int*   lengths   = (const int*)  d_in[4];
    const float* speed     = (const float*)d_in[5];
    const float* W_enc     = (const float*)d_in[6];
    const float* b_enc     = (const float*)d_in[7];
    const float* W_spkr    = (const float*)d_in[8];
    const float* conv_w    = (const float*)d_in[9];
    const float* W_dec     = (const float*)d_in[10];
    const float* W_speed   = (const float*)d_in[11];
    const float* Wp1       = (const float*)d_in[12];
    const float* bp1       = (const float*)d_in[13];
    const float* Wp2       = (const float*)d_in[14];
    const float* bp2       = (const float*)d_in[15];
    const float* W_proj    = (const float*)d_in[16];
    // d_in[17] = b_proj: constant shift, cancels in the masked softmax.

    float* out = (float*)d_out;

    k_front  <<<NB + 128, 256>>>(prev_att, input_dec, spkr, lengths, speed,
                                 W_spkr, W_speed, Wp1, bp1, out);
    k_prenet2<<<dim3(16, 8), 256>>>(Wp2);
    k_window <<<dim3(8, NB), 256>>>(input_enc, prev_att, W_enc, b_enc,
                                    conv_w, W_proj, W_dec, bp2, out);
}